// round 15
// baseline (speedup 1.0000x reference)
#include <cuda_runtime.h>
#include <cuda_fp16.h>
#include <cstddef>
#include <cstdint>

#define NN 50000
#define EE 1600000
#define QQ 16
#define EPSV 1e-8f

// Scratch (allocation-free rule: __device__ globals)
// temp2 stored as fp16 in fragment-permuted col order: 32 B per edge.
__device__ __align__(16) __half2 g_t2a[(size_t)EE * 8];
__device__ __align__(16) __half2 g_t2b[(size_t)EE * 8];
__device__ float g_acc[5][NN * QQ];          // 5 pre-seeded accumulators (permuted)
__device__ __align__(16) uint32_t g_cfrag[32 * 8];  // per-lane split-C fragments

// permuted position p  <->  natural column
__host__ __device__ constexpr int permcol(int p) {
    return 2 * (p >> 2) + (p & 1) + 8 * ((p >> 1) & 1);
}

__device__ __forceinline__ uint32_t pack_h2(float a, float b) {
    __half2 h = __floats2half2_rn(a, b);
    uint32_t u;
    asm("mov.b32 %0, %1;" : "=r"(u) : "r"(*(uint32_t*)&h));
    return u;
}

__device__ __forceinline__ void split_f16(float x, float& hi, float& lo) {
    __half h = __float2half_rn(x);
    hi = __half2float(h);
    lo = x - hi;
}

// packed split of a float pair: hi2 = fp16x2(x0,x1); lo2 = fp16x2(residuals)
__device__ __forceinline__ void split2(float x0, float x1,
                                       uint32_t& hi2, uint32_t& lo2) {
    hi2 = pack_h2(x0, x1);
    __half2 h = *(__half2*)&hi2;
    float2 hf = __half22float2(h);
    lo2 = pack_h2(x0 - hf.x, x1 - hf.y);
}

__device__ __forceinline__ void prefetch_l2(const void* p) {
    asm volatile("prefetch.global.L2 [%0];" :: "l"(p));
}

// one warp: build per-lane split-C fragment table (verified R7/R8 mapping)
__global__ void cfrag_kernel(const float* __restrict__ Cmat,
                             uint32_t* __restrict__ tab)
{
    const int lane = threadIdx.x;
    if (lane >= 32) return;
    const int i4 = lane & 3;
    const int g8 = lane >> 2;
    const int k0 = 2 * i4;
    uint32_t v[8];
    float h00,l00,h01,l01,h10,l10,h11,l11;
#pragma unroll
    for (int nb = 0; nb < 2; nb++) {
        const int n = nb * 8 + g8;
        split_f16(Cmat[(k0    ) * QQ + n], h00, l00);
        split_f16(Cmat[(k0 + 1) * QQ + n], h01, l01);
        split_f16(Cmat[(k0 + 8) * QQ + n], h10, l10);
        split_f16(Cmat[(k0 + 9) * QQ + n], h11, l11);
        v[2*nb + 0] = pack_h2(h00, h01);   // bh(2nb)
        v[2*nb + 1] = pack_h2(h10, h11);   // bh(2nb+1)
        v[4 + 2*nb + 0] = pack_h2(l00, l01); // bl(2nb)
        v[4 + 2*nb + 1] = pack_h2(l10, l11); // bl(2nb+1)
    }
    uint4* tp = (uint4*)(tab + lane * 8);
    tp[0] = make_uint4(v[0], v[1], v[2], v[3]);   // bh0..bh3
    tp[1] = make_uint4(v[4], v[5], v[6], v[7]);   // bl0..bl3
}

// ---------------------------------------------------------------------------
// Fused edge kernel: quad-cooperative rows, fragment-direct, no smem.
// 4 lanes (i4 = lane&3) own one edge row; lane holds natural cols
// {2i4, 2i4+1, 2i4+8, 2i4+9} = its m16n8k16 A-fragment slots.
// R15: register-free L2 prefetch of tile-1's random gather rows, issued
// before tile-0's compute (prefetch.global.L2 holds no destination reg;
// index values are dead immediately after, so the 48-reg optimum survives).
// Precision: split-fp16 Markidis (Ah*Ch + Ah*Cl + Al*Ch, fp32 accum).
// ---------------------------------------------------------------------------
template <bool FIRST, bool LAST>
__global__ void __launch_bounds__(128, 10)
edge_kernel(const float* __restrict__ cav_in,
            const float* __restrict__ marg,      // permuted
            const __half2* __restrict__ t2_cur,  // permuted
            __half2* __restrict__ t2_next,       // permuted
            const int* __restrict__ a1_src,
            const int* __restrict__ indice,
            const int* __restrict__ edge_dst,
            const uint32_t* __restrict__ cfrag,
            float* __restrict__ accum)           // permuted
{
    const int lane = threadIdx.x & 31;
    const int i4   = lane & 3;
    const int g8   = lane >> 2;
    const int base = blockIdx.x * 128 + (threadIdx.x >> 5) * 32;

    // ---- B fragments from table ----
    const uint4* tp = (const uint4*)(cfrag + lane * 8);
    const uint4 bh = __ldg(tp);
    const uint4 bl = __ldg(tp + 1);

    // ---- register-free L2 warm of tile-1's random rows ----
    if (!FIRST) {
        const int eA1 = base + 16 + g8;
        const int sA1 = __ldcs(a1_src + eA1);
        const int sB1 = __ldcs(a1_src + eA1 + 8);
        const int jA1 = __ldcs(indice + eA1);
        const int jB1 = __ldcs(indice + eA1 + 8);
        prefetch_l2(marg + (size_t)sA1 * QQ + 4 * i4);
        prefetch_l2(marg + (size_t)sB1 * QQ + 4 * i4);
        prefetch_l2(t2_cur + (size_t)jA1 * 8 + 2 * i4);
        prefetch_l2(t2_cur + (size_t)jB1 * 8 + 2 * i4);
    }

#define MMA(D, A0, A1, A2, A3, B0, B1) \
    asm volatile("mma.sync.aligned.m16n8k16.row.col.f32.f16.f16.f32 " \
                 "{%0,%1,%2,%3}, {%4,%5,%6,%7}, {%8,%9}, {%0,%1,%2,%3};" \
                 : "+f"(D[0]), "+f"(D[1]), "+f"(D[2]), "+f"(D[3]) \
                 : "r"(A0), "r"(A1), "r"(A2), "r"(A3), "r"(B0), "r"(B1))

#pragma unroll
    for (int T = 0; T < 2; T++) {
        const int eA = base + T * 16 + g8;
        const int eB = eA + 8;
        const int dstA = __ldcs(edge_dst + eA);
        const int dstB = __ldcs(edge_dst + eB);

        float xA[4], xB[4];
        float invA = 1.0f, invB = 1.0f;

        if (FIRST) {
            const float2* pA = (const float2*)(cav_in + (size_t)eA * QQ);
            const float2* pB = (const float2*)(cav_in + (size_t)eB * QQ);
            float2 a0 = __ldcs(pA + i4);
            float2 a1 = __ldcs(pA + 4 + i4);
            float2 b0 = __ldcs(pB + i4);
            float2 b1 = __ldcs(pB + 4 + i4);
            xA[0]=a0.x; xA[1]=a0.y; xA[2]=a1.x; xA[3]=a1.y;
            xB[0]=b0.x; xB[1]=b0.y; xB[2]=b1.x; xB[3]=b1.y;
        } else {
            const int sA = __ldcs(a1_src + eA), sB = __ldcs(a1_src + eB);
            const int jA = __ldcs(indice + eA), jB = __ldcs(indice + eB);
            float4 mA = __ldg((const float4*)(marg + (size_t)sA * QQ + 4 * i4));
            float4 mB = __ldg((const float4*)(marg + (size_t)sB * QQ + 4 * i4));
            uint2 ta = *(const uint2*)(t2_cur + (size_t)jA * 8 + 2 * i4);
            uint2 tb = *(const uint2*)(t2_cur + (size_t)jB * 8 + 2 * i4);
            float2 fa0 = __half22float2(*(__half2*)&ta.x);
            float2 fa1 = __half22float2(*(__half2*)&ta.y);
            float2 fb0 = __half22float2(*(__half2*)&tb.x);
            float2 fb1 = __half22float2(*(__half2*)&tb.y);
            xA[0]=mA.x-fa0.x; xA[1]=mA.y-fa0.y; xA[2]=mA.z-fa1.x; xA[3]=mA.w-fa1.y;
            xB[0]=mB.x-fb0.x; xB[1]=mB.y-fb0.y; xB[2]=mB.z-fb1.x; xB[3]=mB.w-fb1.y;

            float mxA = fmaxf(fmaxf(xA[0], xA[1]), fmaxf(xA[2], xA[3]));
            float mxB = fmaxf(fmaxf(xB[0], xB[1]), fmaxf(xB[2], xB[3]));
            mxA = fmaxf(mxA, __shfl_xor_sync(0xffffffffu, mxA, 1));
            mxA = fmaxf(mxA, __shfl_xor_sync(0xffffffffu, mxA, 2));
            mxB = fmaxf(mxB, __shfl_xor_sync(0xffffffffu, mxB, 1));
            mxB = fmaxf(mxB, __shfl_xor_sync(0xffffffffu, mxB, 2));
            float sAs = 0.f, sBs = 0.f;
#pragma unroll
            for (int q = 0; q < 4; q++) {
                xA[q] = __expf(xA[q] - mxA); sAs += xA[q];
                xB[q] = __expf(xB[q] - mxB); sBs += xB[q];
            }
            sAs += __shfl_xor_sync(0xffffffffu, sAs, 1);
            sAs += __shfl_xor_sync(0xffffffffu, sAs, 2);
            sBs += __shfl_xor_sync(0xffffffffu, sBs, 1);
            sBs += __shfl_xor_sync(0xffffffffu, sBs, 2);
            invA = __fdividef(1.0f, sAs);
            invB = __fdividef(1.0f, sBs);
        }

        // A fragments in registers (hi/lo split)
        uint32_t ah0, ah1, ah2, ah3, al0, al1, al2, al3;
        split2(xA[0], xA[1], ah0, al0);
        split2(xA[2], xA[3], ah2, al2);
        split2(xB[0], xB[1], ah1, al1);
        split2(xB[2], xB[3], ah3, al3);

        float d0[4] = {0.f, 0.f, 0.f, 0.f};
        float d1[4] = {0.f, 0.f, 0.f, 0.f};
        MMA(d0, ah0, ah1, ah2, ah3, bh.x, bh.y);
        MMA(d0, ah0, ah1, ah2, ah3, bl.x, bl.y);
        MMA(d0, al0, al1, al2, al3, bh.x, bh.y);
        MMA(d1, ah0, ah1, ah2, ah3, bh.z, bh.w);
        MMA(d1, ah0, ah1, ah2, ah3, bl.z, bl.w);
        MMA(d1, al0, al1, al2, al3, bh.z, bh.w);

        float oA0 = __logf(fmaf(d0[0], invA, EPSV));   // col 2i4
        float oA1 = __logf(fmaf(d0[1], invA, EPSV));   // col 2i4+1
        float oA2 = __logf(fmaf(d1[0], invA, EPSV));   // col 2i4+8
        float oA3 = __logf(fmaf(d1[1], invA, EPSV));   // col 2i4+9
        float oB0 = __logf(fmaf(d0[2], invB, EPSV));
        float oB1 = __logf(fmaf(d0[3], invB, EPSV));
        float oB2 = __logf(fmaf(d1[2], invB, EPSV));
        float oB3 = __logf(fmaf(d1[3], invB, EPSV));

        if (!LAST) {
            uint2 vA, vB;
            vA.x = pack_h2(oA0, oA1); vA.y = pack_h2(oA2, oA3);
            vB.x = pack_h2(oB0, oB1); vB.y = pack_h2(oB2, oB3);
            *(uint2*)(t2_next + (size_t)eA * 8 + 2 * i4) = vA;
            *(uint2*)(t2_next + (size_t)eB * 8 + 2 * i4) = vB;
        }

        asm volatile("red.global.add.v4.f32 [%0], {%1,%2,%3,%4};"
                     :: "l"(accum + (size_t)dstA * QQ + 4 * i4),
                        "f"(oA0), "f"(oA1), "f"(oA2), "f"(oA3) : "memory");
        asm volatile("red.global.add.v4.f32 [%0], {%1,%2,%3,%4};"
                     :: "l"(accum + (size_t)dstB * QQ + 4 * i4),
                        "f"(oB0), "f"(oB1), "f"(oB2), "f"(oB3) : "memory");
    }
#undef MMA
}

// seed all 5 accumulators with permuted field (one launch)
__global__ void __launch_bounds__(256)
seed_kernel(const float* __restrict__ field, float* __restrict__ acc)
{
    const int n = blockIdx.x * blockDim.x + threadIdx.x;
    if (n >= NN) return;
    const float4* fp = (const float4*)(field + (size_t)n * QQ);
    float4 v[4] = {fp[0], fp[1], fp[2], fp[3]};
    const float* x = (const float*)v;
    float y[QQ];
#pragma unroll
    for (int p = 0; p < QQ; p++) y[p] = x[permcol(p)];
#pragma unroll
    for (int b = 0; b < 5; b++) {
        float4* op = (float4*)(acc + (size_t)b * NN * QQ + (size_t)n * QQ);
#pragma unroll
        for (int g = 0; g < 4; g++) op[g] = ((float4*)y)[g];
    }
}

// out = log_softmax(marg) — read permuted, write natural order
__global__ void __launch_bounds__(256)
out_kernel(const float* __restrict__ marg, float* __restrict__ out)
{
    const int n = blockIdx.x * blockDim.x + threadIdx.x;
    if (n >= NN) return;
    const float4* mp = (const float4*)(marg + (size_t)n * QQ);
    float4 v[4] = {mp[0], mp[1], mp[2], mp[3]};
    const float* x = (const float*)v;
    float mx = x[0];
#pragma unroll
    for (int p = 1; p < QQ; p++) mx = fmaxf(mx, x[p]);
    float s = 0.0f;
#pragma unroll
    for (int p = 0; p < QQ; p++) s += __expf(x[p] - mx);
    const float lse = mx + __logf(s);
    float y[QQ];
#pragma unroll
    for (int p = 0; p < QQ; p++) y[permcol(p)] = x[p] - lse;
    float4* op = (float4*)(out + (size_t)n * QQ);
#pragma unroll
    for (int g = 0; g < 4; g++) op[g] = ((float4*)y)[g];
}

extern "C" void kernel_launch(void* const* d_in, const int* in_sizes, int n_in,
                              void* d_out, int out_size)
{
    // metadata order: marg_i(unused), cav_ij, C, field_i, edge_dst, a1_src, indice_ij
    const float* cav_ij   = (const float*)d_in[1];
    const float* Cmat     = (const float*)d_in[2];
    const float* field_i  = (const float*)d_in[3];
    const int*   edge_dst = (const int*)d_in[4];
    const int*   a1_src   = (const int*)d_in[5];
    const int*   indice   = (const int*)d_in[6];
    float*       out      = (float*)d_out;

    float* acc;
    __half2 *t2a, *t2b;
    uint32_t* cfrag;
    cudaGetSymbolAddress((void**)&acc,   g_acc);
    cudaGetSymbolAddress((void**)&t2a,   g_t2a);
    cudaGetSymbolAddress((void**)&t2b,   g_t2b);
    cudaGetSymbolAddress((void**)&cfrag, g_cfrag);
    float* a0 = acc;
    float* a1 = acc + (size_t)1 * NN * QQ;
    float* a2 = acc + (size_t)2 * NN * QQ;
    float* a3 = acc + (size_t)3 * NN * QQ;
    float* a4 = acc + (size_t)4 * NN * QQ;

    const int EB = 128;
    const int EG = EE / EB;              // 12500 exact
    const int NG = (NN + 255) / 256;

    cfrag_kernel<<<1, 32>>>(Cmat, cfrag);
    seed_kernel<<<NG, 256>>>(field_i, acc);

    edge_kernel<true,  false><<<EG, EB>>>(cav_ij, nullptr, nullptr, t2a,
                                          a1_src, indice, edge_dst, cfrag, a0);
    edge_kernel<false, false><<<EG, EB>>>(nullptr, a0, t2a, t2b,
                                          a1_src, indice, edge_dst, cfrag, a1);
    edge_kernel<false, false><<<EG, EB>>>(nullptr, a1, t2b, t2a,
                                          a1_src, indice, edge_dst, cfrag, a2);
    edge_kernel<false, false><<<EG, EB>>>(nullptr, a2, t2a, t2b,
                                          a1_src, indice, edge_dst, cfrag, a3);
    edge_kernel<false, true ><<<EG, EB>>>(nullptr, a3, t2b, nullptr,
                                          a1_src, indice, edge_dst, cfrag, a4);

    out_kernel<<<NG, 256>>>(a4, out);
}

// round 16
// speedup vs baseline: 1.0910x; 1.0910x over previous
#include <cuda_runtime.h>
#include <cuda_fp16.h>
#include <cstddef>
#include <cstdint>

#define NN 50000
#define EE 1600000
#define QQ 16
#define EPSV 1e-8f

// Scratch (allocation-free rule: __device__ globals)
// temp2 stored as fp16 in fragment-permuted col order: 32 B per edge.
__device__ __align__(16) __half2 g_t2a[(size_t)EE * 8];
__device__ __align__(16) __half2 g_t2b[(size_t)EE * 8];
__device__ float g_acc[5][NN * QQ];          // 5 pre-seeded accumulators (permuted)
__device__ __align__(16) uint32_t g_cfrag[32 * 8];  // per-lane split-C fragments

// permuted position p  <->  natural column
__host__ __device__ constexpr int permcol(int p) {
    return 2 * (p >> 2) + (p & 1) + 8 * ((p >> 1) & 1);
}

__device__ __forceinline__ uint32_t pack_h2(float a, float b) {
    __half2 h = __floats2half2_rn(a, b);
    uint32_t u;
    asm("mov.b32 %0, %1;" : "=r"(u) : "r"(*(uint32_t*)&h));
    return u;
}

__device__ __forceinline__ void split_f16(float x, float& hi, float& lo) {
    __half h = __float2half_rn(x);
    hi = __half2float(h);
    lo = x - hi;
}

// packed split of a float pair: hi2 = fp16x2(x0,x1); lo2 = fp16x2(residuals)
__device__ __forceinline__ void split2(float x0, float x1,
                                       uint32_t& hi2, uint32_t& lo2) {
    hi2 = pack_h2(x0, x1);
    __half2 h = *(__half2*)&hi2;
    float2 hf = __half22float2(h);
    lo2 = pack_h2(x0 - hf.x, x1 - hf.y);
}

// one warp: build per-lane split-C fragment table (verified R7/R8 mapping)
__global__ void cfrag_kernel(const float* __restrict__ Cmat,
                             uint32_t* __restrict__ tab)
{
    const int lane = threadIdx.x;
    if (lane >= 32) return;
    const int i4 = lane & 3;
    const int g8 = lane >> 2;
    const int k0 = 2 * i4;
    uint32_t v[8];
    float h00,l00,h01,l01,h10,l10,h11,l11;
#pragma unroll
    for (int nb = 0; nb < 2; nb++) {
        const int n = nb * 8 + g8;
        split_f16(Cmat[(k0    ) * QQ + n], h00, l00);
        split_f16(Cmat[(k0 + 1) * QQ + n], h01, l01);
        split_f16(Cmat[(k0 + 8) * QQ + n], h10, l10);
        split_f16(Cmat[(k0 + 9) * QQ + n], h11, l11);
        v[2*nb + 0] = pack_h2(h00, h01);   // bh(2nb)
        v[2*nb + 1] = pack_h2(h10, h11);   // bh(2nb+1)
        v[4 + 2*nb + 0] = pack_h2(l00, l01); // bl(2nb)
        v[4 + 2*nb + 1] = pack_h2(l10, l11); // bl(2nb+1)
    }
    uint4* tp = (uint4*)(tab + lane * 8);
    tp[0] = make_uint4(v[0], v[1], v[2], v[3]);   // bh0..bh3
    tp[1] = make_uint4(v[4], v[5], v[6], v[7]);   // bl0..bl3
}

// ---------------------------------------------------------------------------
// Fused edge kernel: quad-cooperative rows, fragment-direct, no smem.
// 4 lanes (i4 = lane&3) own one edge row; lane holds natural cols
// {2i4, 2i4+1, 2i4+8, 2i4+9} = its m16n8k16 A-fragment slots.
// R16 = R14 + evict-first (__ldcs) on the read-once t2 gather, protecting
// unread t2 lines and the write stream in L2. Zero instruction/register
// delta vs the measured R14 optimum.
// Precision: split-fp16 Markidis (Ah*Ch + Ah*Cl + Al*Ch, fp32 accum).
// ---------------------------------------------------------------------------
template <bool FIRST, bool LAST>
__global__ void __launch_bounds__(128, 10)
edge_kernel(const float* __restrict__ cav_in,
            const float* __restrict__ marg,      // permuted
            const __half2* __restrict__ t2_cur,  // permuted
            __half2* __restrict__ t2_next,       // permuted
            const int* __restrict__ a1_src,
            const int* __restrict__ indice,
            const int* __restrict__ edge_dst,
            const uint32_t* __restrict__ cfrag,
            float* __restrict__ accum)           // permuted
{
    const int lane = threadIdx.x & 31;
    const int i4   = lane & 3;
    const int g8   = lane >> 2;
    const int base = blockIdx.x * 128 + (threadIdx.x >> 5) * 32;

    // ---- B fragments from table ----
    const uint4* tp = (const uint4*)(cfrag + lane * 8);
    const uint4 bh = __ldg(tp);
    const uint4 bl = __ldg(tp + 1);

#define MMA(D, A0, A1, A2, A3, B0, B1) \
    asm volatile("mma.sync.aligned.m16n8k16.row.col.f32.f16.f16.f32 " \
                 "{%0,%1,%2,%3}, {%4,%5,%6,%7}, {%8,%9}, {%0,%1,%2,%3};" \
                 : "+f"(D[0]), "+f"(D[1]), "+f"(D[2]), "+f"(D[3]) \
                 : "r"(A0), "r"(A1), "r"(A2), "r"(A3), "r"(B0), "r"(B1))

#pragma unroll
    for (int T = 0; T < 2; T++) {
        const int eA = base + T * 16 + g8;
        const int eB = eA + 8;
        const int dstA = __ldcs(edge_dst + eA);
        const int dstB = __ldcs(edge_dst + eB);

        float xA[4], xB[4];
        float invA = 1.0f, invB = 1.0f;

        if (FIRST) {
            const float2* pA = (const float2*)(cav_in + (size_t)eA * QQ);
            const float2* pB = (const float2*)(cav_in + (size_t)eB * QQ);
            float2 a0 = __ldcs(pA + i4);
            float2 a1 = __ldcs(pA + 4 + i4);
            float2 b0 = __ldcs(pB + i4);
            float2 b1 = __ldcs(pB + 4 + i4);
            xA[0]=a0.x; xA[1]=a0.y; xA[2]=a1.x; xA[3]=a1.y;
            xB[0]=b0.x; xB[1]=b0.y; xB[2]=b1.x; xB[3]=b1.y;
        } else {
            const int sA = __ldcs(a1_src + eA), sB = __ldcs(a1_src + eB);
            const int jA = __ldcs(indice + eA), jB = __ldcs(indice + eB);
            float4 mA = __ldg((const float4*)(marg + (size_t)sA * QQ + 4 * i4));
            float4 mB = __ldg((const float4*)(marg + (size_t)sB * QQ + 4 * i4));
            // read-once random gather: evict-first keeps L2 for unread lines
            uint2 ta = __ldcs((const uint2*)(t2_cur + (size_t)jA * 8 + 2 * i4));
            uint2 tb = __ldcs((const uint2*)(t2_cur + (size_t)jB * 8 + 2 * i4));
            float2 fa0 = __half22float2(*(__half2*)&ta.x);
            float2 fa1 = __half22float2(*(__half2*)&ta.y);
            float2 fb0 = __half22float2(*(__half2*)&tb.x);
            float2 fb1 = __half22float2(*(__half2*)&tb.y);
            xA[0]=mA.x-fa0.x; xA[1]=mA.y-fa0.y; xA[2]=mA.z-fa1.x; xA[3]=mA.w-fa1.y;
            xB[0]=mB.x-fb0.x; xB[1]=mB.y-fb0.y; xB[2]=mB.z-fb1.x; xB[3]=mB.w-fb1.y;

            float mxA = fmaxf(fmaxf(xA[0], xA[1]), fmaxf(xA[2], xA[3]));
            float mxB = fmaxf(fmaxf(xB[0], xB[1]), fmaxf(xB[2], xB[3]));
            mxA = fmaxf(mxA, __shfl_xor_sync(0xffffffffu, mxA, 1));
            mxA = fmaxf(mxA, __shfl_xor_sync(0xffffffffu, mxA, 2));
            mxB = fmaxf(mxB, __shfl_xor_sync(0xffffffffu, mxB, 1));
            mxB = fmaxf(mxB, __shfl_xor_sync(0xffffffffu, mxB, 2));
            float sAs = 0.f, sBs = 0.f;
#pragma unroll
            for (int q = 0; q < 4; q++) {
                xA[q] = __expf(xA[q] - mxA); sAs += xA[q];
                xB[q] = __expf(xB[q] - mxB); sBs += xB[q];
            }
            sAs += __shfl_xor_sync(0xffffffffu, sAs, 1);
            sAs += __shfl_xor_sync(0xffffffffu, sAs, 2);
            sBs += __shfl_xor_sync(0xffffffffu, sBs, 1);
            sBs += __shfl_xor_sync(0xffffffffu, sBs, 2);
            invA = __fdividef(1.0f, sAs);
            invB = __fdividef(1.0f, sBs);
        }

        // A fragments in registers (hi/lo split)
        uint32_t ah0, ah1, ah2, ah3, al0, al1, al2, al3;
        split2(xA[0], xA[1], ah0, al0);
        split2(xA[2], xA[3], ah2, al2);
        split2(xB[0], xB[1], ah1, al1);
        split2(xB[2], xB[3], ah3, al3);

        float d0[4] = {0.f, 0.f, 0.f, 0.f};
        float d1[4] = {0.f, 0.f, 0.f, 0.f};
        MMA(d0, ah0, ah1, ah2, ah3, bh.x, bh.y);
        MMA(d0, ah0, ah1, ah2, ah3, bl.x, bl.y);
        MMA(d0, al0, al1, al2, al3, bh.x, bh.y);
        MMA(d1, ah0, ah1, ah2, ah3, bh.z, bh.w);
        MMA(d1, ah0, ah1, ah2, ah3, bl.z, bl.w);
        MMA(d1, al0, al1, al2, al3, bh.z, bh.w);

        float oA0 = __logf(fmaf(d0[0], invA, EPSV));   // col 2i4
        float oA1 = __logf(fmaf(d0[1], invA, EPSV));   // col 2i4+1
        float oA2 = __logf(fmaf(d1[0], invA, EPSV));   // col 2i4+8
        float oA3 = __logf(fmaf(d1[1], invA, EPSV));   // col 2i4+9
        float oB0 = __logf(fmaf(d0[2], invB, EPSV));
        float oB1 = __logf(fmaf(d0[3], invB, EPSV));
        float oB2 = __logf(fmaf(d1[2], invB, EPSV));
        float oB3 = __logf(fmaf(d1[3], invB, EPSV));

        if (!LAST) {
            uint2 vA, vB;
            vA.x = pack_h2(oA0, oA1); vA.y = pack_h2(oA2, oA3);
            vB.x = pack_h2(oB0, oB1); vB.y = pack_h2(oB2, oB3);
            *(uint2*)(t2_next + (size_t)eA * 8 + 2 * i4) = vA;
            *(uint2*)(t2_next + (size_t)eB * 8 + 2 * i4) = vB;
        }

        asm volatile("red.global.add.v4.f32 [%0], {%1,%2,%3,%4};"
                     :: "l"(accum + (size_t)dstA * QQ + 4 * i4),
                        "f"(oA0), "f"(oA1), "f"(oA2), "f"(oA3) : "memory");
        asm volatile("red.global.add.v4.f32 [%0], {%1,%2,%3,%4};"
                     :: "l"(accum + (size_t)dstB * QQ + 4 * i4),
                        "f"(oB0), "f"(oB1), "f"(oB2), "f"(oB3) : "memory");
    }
#undef MMA
}

// seed all 5 accumulators with permuted field (one launch)
__global__ void __launch_bounds__(256)
seed_kernel(const float* __restrict__ field, float* __restrict__ acc)
{
    const int n = blockIdx.x * blockDim.x + threadIdx.x;
    if (n >= NN) return;
    const float4* fp = (const float4*)(field + (size_t)n * QQ);
    float4 v[4] = {fp[0], fp[1], fp[2], fp[3]};
    const float* x = (const float*)v;
    float y[QQ];
#pragma unroll
    for (int p = 0; p < QQ; p++) y[p] = x[permcol(p)];
#pragma unroll
    for (int b = 0; b < 5; b++) {
        float4* op = (float4*)(acc + (size_t)b * NN * QQ + (size_t)n * QQ);
#pragma unroll
        for (int g = 0; g < 4; g++) op[g] = ((float4*)y)[g];
    }
}

// out = log_softmax(marg) — read permuted, write natural order
__global__ void __launch_bounds__(256)
out_kernel(const float* __restrict__ marg, float* __restrict__ out)
{
    const int n = blockIdx.x * blockDim.x + threadIdx.x;
    if (n >= NN) return;
    const float4* mp = (const float4*)(marg + (size_t)n * QQ);
    float4 v[4] = {mp[0], mp[1], mp[2], mp[3]};
    const float* x = (const float*)v;
    float mx = x[0];
#pragma unroll
    for (int p = 1; p < QQ; p++) mx = fmaxf(mx, x[p]);
    float s = 0.0f;
#pragma unroll
    for (int p = 0; p < QQ; p++) s += __expf(x[p] - mx);
    const float lse = mx + __logf(s);
    float y[QQ];
#pragma unroll
    for (int p = 0; p < QQ; p++) y[permcol(p)] = x[p] - lse;
    float4* op = (float4*)(out + (size_t)n * QQ);
#pragma unroll
    for (int g = 0; g < 4; g++) op[g] = ((float4*)y)[g];
}

extern "C" void kernel_launch(void* const* d_in, const int* in_sizes, int n_in,
                              void* d_out, int out_size)
{
    // metadata order: marg_i(unused), cav_ij, C, field_i, edge_dst, a1_src, indice_ij
    const float* cav_ij   = (const float*)d_in[1];
    const float* Cmat     = (const float*)d_in[2];
    const float* field_i  = (const float*)d_in[3];
    const int*   edge_dst = (const int*)d_in[4];
    const int*   a1_src   = (const int*)d_in[5];
    const int*   indice   = (const int*)d_in[6];
    float*       out      = (float*)d_out;

    float* acc;
    __half2 *t2a, *t2b;
    uint32_t* cfrag;
    cudaGetSymbolAddress((void**)&acc,   g_acc);
    cudaGetSymbolAddress((void**)&t2a,   g_t2a);
    cudaGetSymbolAddress((void**)&t2b,   g_t2b);
    cudaGetSymbolAddress((void**)&cfrag, g_cfrag);
    float* a0 = acc;
    float* a1 = acc + (size_t)1 * NN * QQ;
    float* a2 = acc + (size_t)2 * NN * QQ;
    float* a3 = acc + (size_t)3 * NN * QQ;
    float* a4 = acc + (size_t)4 * NN * QQ;

    const int EB = 128;
    const int EG = EE / EB;              // 12500 exact
    const int NG = (NN + 255) / 256;

    cfrag_kernel<<<1, 32>>>(Cmat, cfrag);
    seed_kernel<<<NG, 256>>>(field_i, acc);

    edge_kernel<true,  false><<<EG, EB>>>(cav_ij, nullptr, nullptr, t2a,
                                          a1_src, indice, edge_dst, cfrag, a0);
    edge_kernel<false, false><<<EG, EB>>>(nullptr, a0, t2a, t2b,
                                          a1_src, indice, edge_dst, cfrag, a1);
    edge_kernel<false, false><<<EG, EB>>>(nullptr, a1, t2b, t2a,
                                          a1_src, indice, edge_dst, cfrag, a2);
    edge_kernel<false, false><<<EG, EB>>>(nullptr, a2, t2a, t2b,
                                          a1_src, indice, edge_dst, cfrag, a3);
    edge_kernel<false, true ><<<EG, EB>>>(nullptr, a3, t2b, nullptr,
                                          a1_src, indice, edge_dst, cfrag, a4);

    out_kernel<<<NG, 256>>>(a4, out);
}

// round 17
// speedup vs baseline: 1.1106x; 1.0180x over previous
#include <cuda_runtime.h>
#include <cuda_fp16.h>
#include <cstddef>
#include <cstdint>

#define NN 50000
#define EE 1600000
#define QQ 16
#define EPSV 1e-8f

// Scratch (allocation-free rule: __device__ globals)
// temp2 stored as fp16 in fragment-permuted col order: 32 B per edge.
__device__ __align__(16) __half2 g_t2a[(size_t)EE * 8];
__device__ __align__(16) __half2 g_t2b[(size_t)EE * 8];
__device__ float g_acc[5][NN * QQ];          // 5 pre-seeded accumulators (permuted)
__device__ __align__(16) uint32_t g_cfrag[32 * 8];  // per-lane split-C fragments

// permuted position p  <->  natural column
__host__ __device__ constexpr int permcol(int p) {
    return 2 * (p >> 2) + (p & 1) + 8 * ((p >> 1) & 1);
}

__device__ __forceinline__ uint32_t pack_h2(float a, float b) {
    __half2 h = __floats2half2_rn(a, b);
    uint32_t u;
    asm("mov.b32 %0, %1;" : "=r"(u) : "r"(*(uint32_t*)&h));
    return u;
}

__device__ __forceinline__ void split_f16(float x, float& hi, float& lo) {
    __half h = __float2half_rn(x);
    hi = __half2float(h);
    lo = x - hi;
}

// packed split of a float pair: hi2 = fp16x2(x0,x1); lo2 = fp16x2(residuals)
__device__ __forceinline__ void split2(float x0, float x1,
                                       uint32_t& hi2, uint32_t& lo2) {
    hi2 = pack_h2(x0, x1);
    __half2 h = *(__half2*)&hi2;
    float2 hf = __half22float2(h);
    lo2 = pack_h2(x0 - hf.x, x1 - hf.y);
}

// ---------------------------------------------------------------------------
// Fused edge kernel: quad-cooperative rows, fragment-direct, no smem.
// 4 lanes (i4 = lane&3) own one edge row; lane holds natural cols
// {2i4, 2i4+1, 2i4+8, 2i4+9} = its m16n8k16 A-fragment slots.
// B fragments held in registers from the precomputed table.
// Precision: split-fp16 Markidis (Ah*Ch + Ah*Cl + Al*Ch, fp32 accum).
// R17: 64-thread blocks, 20/SM — same 40 warps/SM and 48 regs as the R14
// optimum, finer scheduling granularity.
// ---------------------------------------------------------------------------
template <bool FIRST, bool LAST>
__global__ void __launch_bounds__(64, 20)
edge_kernel(const float* __restrict__ cav_in,
            const float* __restrict__ marg,      // permuted
            const __half2* __restrict__ t2_cur,  // permuted
            __half2* __restrict__ t2_next,       // permuted
            const int* __restrict__ a1_src,
            const int* __restrict__ indice,
            const int* __restrict__ edge_dst,
            const uint32_t* __restrict__ cfrag,
            float* __restrict__ accum)           // permuted
{
    const int lane = threadIdx.x & 31;
    const int i4   = lane & 3;
    const int g8   = lane >> 2;
    const int base = blockIdx.x * 64 + (threadIdx.x >> 5) * 32;

    // ---- B fragments from table ----
    const uint4* tp = (const uint4*)(cfrag + lane * 8);
    const uint4 bh = __ldg(tp);
    const uint4 bl = __ldg(tp + 1);

#define MMA(D, A0, A1, A2, A3, B0, B1) \
    asm volatile("mma.sync.aligned.m16n8k16.row.col.f32.f16.f16.f32 " \
                 "{%0,%1,%2,%3}, {%4,%5,%6,%7}, {%8,%9}, {%0,%1,%2,%3};" \
                 : "+f"(D[0]), "+f"(D[1]), "+f"(D[2]), "+f"(D[3]) \
                 : "r"(A0), "r"(A1), "r"(A2), "r"(A3), "r"(B0), "r"(B1))

#pragma unroll
    for (int T = 0; T < 2; T++) {
        const int eA = base + T * 16 + g8;
        const int eB = eA + 8;
        const int dstA = __ldcs(edge_dst + eA);
        const int dstB = __ldcs(edge_dst + eB);

        float xA[4], xB[4];
        float invA = 1.0f, invB = 1.0f;

        if (FIRST) {
            const float2* pA = (const float2*)(cav_in + (size_t)eA * QQ);
            const float2* pB = (const float2*)(cav_in + (size_t)eB * QQ);
            float2 a0 = __ldcs(pA + i4);
            float2 a1 = __ldcs(pA + 4 + i4);
            float2 b0 = __ldcs(pB + i4);
            float2 b1 = __ldcs(pB + 4 + i4);
            xA[0]=a0.x; xA[1]=a0.y; xA[2]=a1.x; xA[3]=a1.y;
            xB[0]=b0.x; xB[1]=b0.y; xB[2]=b1.x; xB[3]=b1.y;
        } else {
            const int sA = __ldcs(a1_src + eA), sB = __ldcs(a1_src + eB);
            const int jA = __ldcs(indice + eA), jB = __ldcs(indice + eB);
            float4 mA = __ldg((const float4*)(marg + (size_t)sA * QQ + 4 * i4));
            float4 mB = __ldg((const float4*)(marg + (size_t)sB * QQ + 4 * i4));
            uint2 ta = *(const uint2*)(t2_cur + (size_t)jA * 8 + 2 * i4);
            uint2 tb = *(const uint2*)(t2_cur + (size_t)jB * 8 + 2 * i4);
            float2 fa0 = __half22float2(*(__half2*)&ta.x);
            float2 fa1 = __half22float2(*(__half2*)&ta.y);
            float2 fb0 = __half22float2(*(__half2*)&tb.x);
            float2 fb1 = __half22float2(*(__half2*)&tb.y);
            xA[0]=mA.x-fa0.x; xA[1]=mA.y-fa0.y; xA[2]=mA.z-fa1.x; xA[3]=mA.w-fa1.y;
            xB[0]=mB.x-fb0.x; xB[1]=mB.y-fb0.y; xB[2]=mB.z-fb1.x; xB[3]=mB.w-fb1.y;

            float mxA = fmaxf(fmaxf(xA[0], xA[1]), fmaxf(xA[2], xA[3]));
            float mxB = fmaxf(fmaxf(xB[0], xB[1]), fmaxf(xB[2], xB[3]));
            mxA = fmaxf(mxA, __shfl_xor_sync(0xffffffffu, mxA, 1));
            mxA = fmaxf(mxA, __shfl_xor_sync(0xffffffffu, mxA, 2));
            mxB = fmaxf(mxB, __shfl_xor_sync(0xffffffffu, mxB, 1));
            mxB = fmaxf(mxB, __shfl_xor_sync(0xffffffffu, mxB, 2));
            float sAs = 0.f, sBs = 0.f;
#pragma unroll
            for (int q = 0; q < 4; q++) {
                xA[q] = __expf(xA[q] - mxA); sAs += xA[q];
                xB[q] = __expf(xB[q] - mxB); sBs += xB[q];
            }
            sAs += __shfl_xor_sync(0xffffffffu, sAs, 1);
            sAs += __shfl_xor_sync(0xffffffffu, sAs, 2);
            sBs += __shfl_xor_sync(0xffffffffu, sBs, 1);
            sBs += __shfl_xor_sync(0xffffffffu, sBs, 2);
            invA = __fdividef(1.0f, sAs);
            invB = __fdividef(1.0f, sBs);
        }

        // A fragments in registers (hi/lo split)
        uint32_t ah0, ah1, ah2, ah3, al0, al1, al2, al3;
        split2(xA[0], xA[1], ah0, al0);
        split2(xA[2], xA[3], ah2, al2);
        split2(xB[0], xB[1], ah1, al1);
        split2(xB[2], xB[3], ah3, al3);

        float d0[4] = {0.f, 0.f, 0.f, 0.f};
        float d1[4] = {0.f, 0.f, 0.f, 0.f};
        MMA(d0, ah0, ah1, ah2, ah3, bh.x, bh.y);
        MMA(d0, ah0, ah1, ah2, ah3, bl.x, bl.y);
        MMA(d0, al0, al1, al2, al3, bh.x, bh.y);
        MMA(d1, ah0, ah1, ah2, ah3, bh.z, bh.w);
        MMA(d1, ah0, ah1, ah2, ah3, bl.z, bl.w);
        MMA(d1, al0, al1, al2, al3, bh.z, bh.w);

        float oA0 = __logf(fmaf(d0[0], invA, EPSV));   // col 2i4
        float oA1 = __logf(fmaf(d0[1], invA, EPSV));   // col 2i4+1
        float oA2 = __logf(fmaf(d1[0], invA, EPSV));   // col 2i4+8
        float oA3 = __logf(fmaf(d1[1], invA, EPSV));   // col 2i4+9
        float oB0 = __logf(fmaf(d0[2], invB, EPSV));
        float oB1 = __logf(fmaf(d0[3], invB, EPSV));
        float oB2 = __logf(fmaf(d1[2], invB, EPSV));
        float oB3 = __logf(fmaf(d1[3], invB, EPSV));

        if (!LAST) {
            uint2 vA, vB;
            vA.x = pack_h2(oA0, oA1); vA.y = pack_h2(oA2, oA3);
            vB.x = pack_h2(oB0, oB1); vB.y = pack_h2(oB2, oB3);
            *(uint2*)(t2_next + (size_t)eA * 8 + 2 * i4) = vA;
            *(uint2*)(t2_next + (size_t)eB * 8 + 2 * i4) = vB;
        }

        asm volatile("red.global.add.v4.f32 [%0], {%1,%2,%3,%4};"
                     :: "l"(accum + (size_t)dstA * QQ + 4 * i4),
                        "f"(oA0), "f"(oA1), "f"(oA2), "f"(oA3) : "memory");
        asm volatile("red.global.add.v4.f32 [%0], {%1,%2,%3,%4};"
                     :: "l"(accum + (size_t)dstB * QQ + 4 * i4),
                        "f"(oB0), "f"(oB1), "f"(oB2), "f"(oB3) : "memory");
    }
#undef MMA
}

// seed all 5 accumulators with permuted field; block 0 also builds the
// split-C fragment table (folds the former cfrag_kernel launch in)
__global__ void __launch_bounds__(256)
seed_kernel(const float* __restrict__ field, float* __restrict__ acc,
            const float* __restrict__ Cmat, uint32_t* __restrict__ tab)
{
    if (blockIdx.x == 0 && threadIdx.x < 32) {
        const int lane = threadIdx.x;
        const int i4 = lane & 3;
        const int g8 = lane >> 2;
        const int k0 = 2 * i4;
        uint32_t v[8];
        float h00,l00,h01,l01,h10,l10,h11,l11;
#pragma unroll
        for (int nb = 0; nb < 2; nb++) {
            const int n = nb * 8 + g8;
            split_f16(Cmat[(k0    ) * QQ + n], h00, l00);
            split_f16(Cmat[(k0 + 1) * QQ + n], h01, l01);
            split_f16(Cmat[(k0 + 8) * QQ + n], h10, l10);
            split_f16(Cmat[(k0 + 9) * QQ + n], h11, l11);
            v[2*nb + 0] = pack_h2(h00, h01);
            v[2*nb + 1] = pack_h2(h10, h11);
            v[4 + 2*nb + 0] = pack_h2(l00, l01);
            v[4 + 2*nb + 1] = pack_h2(l10, l11);
        }
        uint4* tp = (uint4*)(tab + lane * 8);
        tp[0] = make_uint4(v[0], v[1], v[2], v[3]);
        tp[1] = make_uint4(v[4], v[5], v[6], v[7]);
    }

    const int n = blockIdx.x * blockDim.x + threadIdx.x;
    if (n >= NN) return;
    const float4* fp = (const float4*)(field + (size_t)n * QQ);
    float4 v[4] = {fp[0], fp[1], fp[2], fp[3]};
    const float* x = (const float*)v;
    float y[QQ];
#pragma unroll
    for (int p = 0; p < QQ; p++) y[p] = x[permcol(p)];
#pragma unroll
    for (int b = 0; b < 5; b++) {
        float4* op = (float4*)(acc + (size_t)b * NN * QQ + (size_t)n * QQ);
#pragma unroll
        for (int g = 0; g < 4; g++) op[g] = ((float4*)y)[g];
    }
}

// out = log_softmax(marg) — read permuted, write natural order
__global__ void __launch_bounds__(256)
out_kernel(const float* __restrict__ marg, float* __restrict__ out)
{
    const int n = blockIdx.x * blockDim.x + threadIdx.x;
    if (n >= NN) return;
    const float4* mp = (const float4*)(marg + (size_t)n * QQ);
    float4 v[4] = {mp[0], mp[1], mp[2], mp[3]};
    const float* x = (const float*)v;
    float mx = x[0];
#pragma unroll
    for (int p = 1; p < QQ; p++) mx = fmaxf(mx, x[p]);
    float s = 0.0f;
#pragma unroll
    for (int p = 0; p < QQ; p++) s += __expf(x[p] - mx);
    const float lse = mx + __logf(s);
    float y[QQ];
#pragma unroll
    for (int p = 0; p < QQ; p++) y[permcol(p)] = x[p] - lse;
    float4* op = (float4*)(out + (size_t)n * QQ);
#pragma unroll
    for (int g = 0; g < 4; g++) op[g] = ((float4*)y)[g];
}

extern "C" void kernel_launch(void* const* d_in, const int* in_sizes, int n_in,
                              void* d_out, int out_size)
{
    // metadata order: marg_i(unused), cav_ij, C, field_i, edge_dst, a1_src, indice_ij
    const float* cav_ij   = (const float*)d_in[1];
    const float* Cmat     = (const float*)d_in[2];
    const float* field_i  = (const float*)d_in[3];
    const int*   edge_dst = (const int*)d_in[4];
    const int*   a1_src   = (const int*)d_in[5];
    const int*   indice   = (const int*)d_in[6];
    float*       out      = (float*)d_out;

    float* acc;
    __half2 *t2a, *t2b;
    uint32_t* cfrag;
    cudaGetSymbolAddress((void**)&acc,   g_acc);
    cudaGetSymbolAddress((void**)&t2a,   g_t2a);
    cudaGetSymbolAddress((void**)&t2b,   g_t2b);
    cudaGetSymbolAddress((void**)&cfrag, g_cfrag);
    float* a0 = acc;
    float* a1 = acc + (size_t)1 * NN * QQ;
    float* a2 = acc + (size_t)2 * NN * QQ;
    float* a3 = acc + (size_t)3 * NN * QQ;
    float* a4 = acc + (size_t)4 * NN * QQ;

    const int EB = 64;
    const int EG = EE / EB;              // 25000 exact
    const int NG = (NN + 255) / 256;

    seed_kernel<<<NG, 256>>>(field_i, acc, Cmat, cfrag);

    edge_kernel<true,  false><<<EG, EB>>>(cav_ij, nullptr, nullptr, t2a,
                                          a1_src, indice, edge_dst, cfrag, a0);
    edge_kernel<false, false><<<EG, EB>>>(nullptr, a0, t2a, t2b,
                                          a1_src, indice, edge_dst, cfrag, a1);
    edge_kernel<false, false><<<EG, EB>>>(nullptr, a1, t2b, t2a,
                                          a1_src, indice, edge_dst, cfrag, a2);
    edge_kernel<false, false><<<EG, EB>>>(nullptr, a2, t2a, t2b,
                                          a1_src, indice, edge_dst, cfrag, a3);
    edge_kernel<false, true ><<<EG, EB>>>(nullptr, a3, t2b, nullptr,
                                          a1_src, indice, edge_dst, cfrag, a4);

    out_kernel<<<NG, 256>>>(a4, out);
}